// round 1
// baseline (speedup 1.0000x reference)
#include <cuda_runtime.h>
#include <cstdint>

#define NN 32768
#define HH 2048
#define DD 256
#define KK 4096

// ---------------- scratch (static device globals; no runtime allocation) ----
__device__ float g_z[NN * DD];        // 32 MB: pre-projection output
__device__ int   g_idx[NN];           // argmin indices
__device__ float g_cnorm[KK];         // ||codebook_k||^2
__device__ float g_partial[256];      // vq-loss partial sums

// ---------------- GEMM-NT tiling ----------------
#define BM 128
#define BN 64
#define BKT 16
#define TM 8
#define TN 4
// 256 threads: tx in [0,16) over columns, ty in [0,16) over rows

// C[m,n] = sum_k A[m,k] * B[n,k] + bias[n]
// PRE  = true : A = embed, C = g_z (Nd=DD, Kd=HH)
// PRE  = false: A = codebook gathered via g_idx, C = Cout (Nd=HH, Kd=DD)
template <bool PRE>
__global__ __launch_bounds__(256) void gemm_nt(
    const float* __restrict__ A, const float* __restrict__ B,
    const float* __restrict__ bias, float* __restrict__ Cout,
    int Nd, int Kd)
{
    __shared__ float As[BKT][BM];
    __shared__ float Bs[BKT][BN];
    __shared__ int   rmap[BM];

    const int tid = threadIdx.x;
    const int tx = tid & 15;
    const int ty = tid >> 4;
    const int m0 = blockIdx.y * BM;
    const int n0 = blockIdx.x * BN;

    if (!PRE) {
        if (tid < BM) rmap[tid] = g_idx[m0 + tid];
    }
    __syncthreads();

    float acc[TM][TN];
#pragma unroll
    for (int i = 0; i < TM; i++)
#pragma unroll
        for (int j = 0; j < TN; j++) acc[i][j] = 0.f;

    for (int kk = 0; kk < Kd; kk += BKT) {
        // load A tile: 512 float4 total, 2 per thread
#pragma unroll
        for (int l = 0; l < 2; l++) {
            int lin = tid + l * 256;          // 0..511
            int r = lin >> 2;                 // 0..127
            int q = lin & 3;                  // 0..3
            const float* arow;
            if (PRE) arow = A + (size_t)(m0 + r) * Kd;
            else     arow = A + (size_t)rmap[r] * Kd;
            float4 v = *(const float4*)(arow + kk + q * 4);
            As[q * 4 + 0][r] = v.x;
            As[q * 4 + 1][r] = v.y;
            As[q * 4 + 2][r] = v.z;
            As[q * 4 + 3][r] = v.w;
        }
        // load B tile: 256 float4, 1 per thread
        {
            int r = tid >> 2;
            int q = tid & 3;
            float4 v = *(const float4*)(B + (size_t)(n0 + r) * Kd + kk + q * 4);
            Bs[q * 4 + 0][r] = v.x;
            Bs[q * 4 + 1][r] = v.y;
            Bs[q * 4 + 2][r] = v.z;
            Bs[q * 4 + 3][r] = v.w;
        }
        __syncthreads();
#pragma unroll
        for (int k = 0; k < BKT; k++) {
            float a[TM], b[TN];
#pragma unroll
            for (int i = 0; i < TM; i++) a[i] = As[k][ty * TM + i];
#pragma unroll
            for (int j = 0; j < TN; j++) b[j] = Bs[k][tx * TN + j];
#pragma unroll
            for (int i = 0; i < TM; i++)
#pragma unroll
                for (int j = 0; j < TN; j++)
                    acc[i][j] = fmaf(a[i], b[j], acc[i][j]);
        }
        __syncthreads();
    }

    float* C = PRE ? g_z : Cout;
    float bj[TN];
#pragma unroll
    for (int j = 0; j < TN; j++) bj[j] = bias[n0 + tx * TN + j];
#pragma unroll
    for (int i = 0; i < TM; i++) {
        size_t m = (size_t)(m0 + ty * TM + i);
        float4 r;
        r.x = acc[i][0] + bj[0];
        r.y = acc[i][1] + bj[1];
        r.z = acc[i][2] + bj[2];
        r.w = acc[i][3] + bj[3];
        *(float4*)&C[m * Nd + n0 + tx * TN] = r;
    }
}

// ---------------- codebook squared norms ----------------
__global__ __launch_bounds__(256) void cnorm_kernel(const float* __restrict__ CB)
{
    int w = threadIdx.x >> 5;
    int lane = threadIdx.x & 31;
    int row = blockIdx.x * 8 + w;
    const float4* p = (const float4*)(CB + (size_t)row * DD);
    float s = 0.f;
#pragma unroll
    for (int i = 0; i < 2; i++) {
        float4 v = p[lane + i * 32];
        s += v.x * v.x + v.y * v.y + v.z * v.z + v.w * v.w;
    }
#pragma unroll
    for (int o = 16; o; o >>= 1) s += __shfl_xor_sync(0xFFFFFFFFu, s, o);
    if (!lane) g_cnorm[row] = s;
}

// ---------------- fused distance GEMM + argmin ----------------
// score(n,k) = ||c_k||^2 - 2 * z_n . c_k   (||z||^2 dropped: row-constant)
__global__ __launch_bounds__(256) void argmin_kernel(const float* __restrict__ CB,
                                                     float* __restrict__ out_idx)
{
    __shared__ float As[BKT][BM];
    __shared__ float Bs[BKT][BN];

    const int tid = threadIdx.x;
    const int tx = tid & 15;
    const int ty = tid >> 4;
    const int m0 = blockIdx.x * BM;

    unsigned long long runmin[TM];
#pragma unroll
    for (int i = 0; i < TM; i++) runmin[i] = ~0ULL;

    for (int c0 = 0; c0 < KK; c0 += BN) {
        float acc[TM][TN];
#pragma unroll
        for (int i = 0; i < TM; i++)
#pragma unroll
            for (int j = 0; j < TN; j++) acc[i][j] = 0.f;

        for (int kk = 0; kk < DD; kk += BKT) {
#pragma unroll
            for (int l = 0; l < 2; l++) {
                int lin = tid + l * 256;
                int r = lin >> 2;
                int q = lin & 3;
                float4 v = *(const float4*)(g_z + (size_t)(m0 + r) * DD + kk + q * 4);
                As[q * 4 + 0][r] = v.x;
                As[q * 4 + 1][r] = v.y;
                As[q * 4 + 2][r] = v.z;
                As[q * 4 + 3][r] = v.w;
            }
            {
                int r = tid >> 2;
                int q = tid & 3;
                float4 v = *(const float4*)(CB + (size_t)(c0 + r) * DD + kk + q * 4);
                Bs[q * 4 + 0][r] = v.x;
                Bs[q * 4 + 1][r] = v.y;
                Bs[q * 4 + 2][r] = v.z;
                Bs[q * 4 + 3][r] = v.w;
            }
            __syncthreads();
#pragma unroll
            for (int k = 0; k < BKT; k++) {
                float a[TM], b[TN];
#pragma unroll
                for (int i = 0; i < TM; i++) a[i] = As[k][ty * TM + i];
#pragma unroll
                for (int j = 0; j < TN; j++) b[j] = Bs[k][tx * TN + j];
#pragma unroll
                for (int i = 0; i < TM; i++)
#pragma unroll
                    for (int j = 0; j < TN; j++)
                        acc[i][j] = fmaf(a[i], b[j], acc[i][j]);
            }
            __syncthreads();
        }
        // update per-row running min with order-preserving packed keys
        float cn[TN];
#pragma unroll
        for (int j = 0; j < TN; j++) cn[j] = g_cnorm[c0 + tx * TN + j];
#pragma unroll
        for (int i = 0; i < TM; i++) {
#pragma unroll
            for (int j = 0; j < TN; j++) {
                float score = cn[j] - 2.0f * acc[i][j];
                unsigned u = __float_as_uint(score);
                u = (u & 0x80000000u) ? ~u : (u | 0x80000000u);
                unsigned long long key =
                    ((unsigned long long)u << 32) | (unsigned)(c0 + tx * TN + j);
                if (key < runmin[i]) runmin[i] = key;
            }
        }
    }

    // each row owned by exactly one warp-half (16 lanes, tx = lane & 15):
    // butterfly-min over tx, then lane tx==0 writes
#pragma unroll
    for (int i = 0; i < TM; i++) {
        unsigned long long v = runmin[i];
#pragma unroll
        for (int s = 1; s < 16; s <<= 1) {
            unsigned long long o = __shfl_xor_sync(0xFFFFFFFFu, v, s);
            if (o < v) v = o;
        }
        if (tx == 0) {
            int row = m0 + ty * TM + i;
            int idx = (int)(v & 0xFFFFFFFFu);
            g_idx[row] = idx;
            out_idx[row] = (float)idx;
        }
    }
}

// ---------------- vq loss partial sums: sum (z_q - z)^2 ----------------
__global__ __launch_bounds__(256) void vq_partial(const float* __restrict__ CB)
{
    __shared__ float red[256];
    const int tid = threadIdx.x;
    const int bid = blockIdx.x;          // 256 blocks, 128 rows each
    const int sub = tid >> 6;            // 0..3
    const int d4 = tid & 63;             // 0..63
    float acc = 0.f;
    for (int rr = 0; rr < 32; rr++) {
        int row = bid * 128 + rr * 4 + sub;
        int code = g_idx[row];
        float4 zv = *(const float4*)(g_z + (size_t)row * DD + d4 * 4);
        float4 cv = *(const float4*)(CB + (size_t)code * DD + d4 * 4);
        float dx = cv.x - zv.x, dy = cv.y - zv.y;
        float dz = cv.z - zv.z, dw = cv.w - zv.w;
        acc += dx * dx + dy * dy + dz * dz + dw * dw;
    }
    red[tid] = acc;
    __syncthreads();
    for (int s = 128; s; s >>= 1) {
        if (tid < s) red[tid] += red[tid + s];
        __syncthreads();
    }
    if (!tid) g_partial[bid] = red[0];
}

// ---------------- finalize: log-softmax rate + vq loss scalars ----------------
__global__ __launch_bounds__(1024) void finalize_kernel(const float* __restrict__ prior,
                                                        float* __restrict__ out)
{
    __shared__ float red[1024];
    const int tid = threadIdx.x;

    // max of prior
    float m = -1e30f;
    for (int k = tid; k < KK; k += 1024) m = fmaxf(m, prior[k]);
    red[tid] = m;
    __syncthreads();
    for (int s = 512; s; s >>= 1) {
        if (tid < s) red[tid] = fmaxf(red[tid], red[tid + s]);
        __syncthreads();
    }
    float mx = red[0];
    __syncthreads();

    // sum exp
    float se = 0.f;
    for (int k = tid; k < KK; k += 1024) se += expf(prior[k] - mx);
    red[tid] = se;
    __syncthreads();
    for (int s = 512; s; s >>= 1) {
        if (tid < s) red[tid] += red[tid + s];
        __syncthreads();
    }
    float logZ = mx + logf(red[0]);
    __syncthreads();

    // sum of prior[idx]
    float sp = 0.f;
    for (int n = tid; n < NN; n += 1024) sp += prior[g_idx[n]];
    red[tid] = sp;
    __syncthreads();
    for (int s = 512; s; s >>= 1) {
        if (tid < s) red[tid] += red[tid + s];
        __syncthreads();
    }
    float SP = red[0];
    __syncthreads();

    // vq partial sum
    red[tid] = (tid < 256) ? g_partial[tid] : 0.f;
    __syncthreads();
    for (int s = 512; s; s >>= 1) {
        if (tid < s) red[tid] += red[tid + s];
        __syncthreads();
    }
    if (!tid) {
        float rate = ((float)NN * logZ - SP) * 1.4426950408889634f;  // / ln 2
        float vq = 1.25f * red[0] / ((float)NN * (float)DD);
        out[(size_t)NN * HH + NN]     = rate;
        out[(size_t)NN * HH + NN + 1] = vq;
    }
}

// ---------------- launch ----------------
extern "C" void kernel_launch(void* const* d_in, const int* in_sizes, int n_in,
                              void* d_out, int out_size)
{
    const float* embed    = (const float*)d_in[0];
    const float* pre_w    = (const float*)d_in[1];
    const float* pre_b    = (const float*)d_in[2];
    const float* codebook = (const float*)d_in[3];
    const float* post_w   = (const float*)d_in[4];
    const float* post_b   = (const float*)d_in[5];
    const float* prior    = (const float*)d_in[6];
    float* out = (float*)d_out;

    // codebook norms (independent)
    cnorm_kernel<<<KK / 8, 256>>>(codebook);

    // z = embed @ pre_w.T + pre_b   -> g_z
    gemm_nt<true><<<dim3(DD / BN, NN / BM), 256>>>(embed, pre_w, pre_b, nullptr, DD, HH);

    // fused distance + argmin -> g_idx, out[N*H ..)
    argmin_kernel<<<NN / BM, 256>>>(codebook, out + (size_t)NN * HH);

    // embed_hat = codebook[idx] @ post_w.T + post_b -> out[0 .. N*H)
    gemm_nt<false><<<dim3(HH / BN, NN / BM), 256>>>(codebook, post_w, post_b, out, HH, DD);

    // vq loss partials, then scalars
    vq_partial<<<256, 256>>>(codebook);
    finalize_kernel<<<1, 1024>>>(prior, out);
}